// round 11
// baseline (speedup 1.0000x reference)
#include <cuda_runtime.h>
#include <cstdint>

#define IN_DIM   4096
#define OUT_DIM  1024
#define N_ROWS   16384
#define NCH      16
#define CCOLS    256
#define TILE_N   128
#define XSTRIDE  148                    // words/col: %32==20 -> conflict-free STS/LDS.128
#define COLBYTES (XSTRIDE * 4)          // 592
#define DUMMY_OFF (CCOLS * COLBYTES)    // 151552: zero column
#define XS_WORDS  ((CCOLS + 1) * XSTRIDE)
#define ENT_OFF   152144                // bytes, 16B aligned (= XS_WORDS*4 rounded up)
#define ENT_BYTES (256 * 4 * 4)         // 4 KB: 4 fixed entries x 256 rows
#define SMEM_TOTAL (ENT_OFF + ENT_BYTES)
#define OUT_STRIDE 257
#define THREADS  1024
#define RPC      256
#define RPW      8
#define NRB      (OUT_DIM / RPC)        // 4
#define OVS      12                     // overflow staging slots per (row,chunk)
#define BKT      24                     // packed overflow slots per (chunk,rblock,warp)

// fixed entry / overflow entry: col*592 | sign<<31 ; overflow also carries (row&7)<<1
__device__ uint32_t g_fix[NCH][OUT_DIM][4];
__device__ uint32_t g_ovstage[OUT_DIM][NCH][OVS];
__device__ uint8_t  g_ovscnt[OUT_DIM][NCH];
__device__ uint32_t g_ov[NCH][NRB][32][BKT];
__device__ uint8_t  g_ovc[NCH][NRB][32];
__device__ float    g_mag;

// ---------------------------------------------------------------------------
// Build A: one warp per (row, chunk) segment -> 16K warps (fast, ~5us).
// First 4 entries to fixed slots (dummy-padded), rest staged per-row. Determ.
// ---------------------------------------------------------------------------
__global__ void __launch_bounds__(256) build_a(const float* __restrict__ Phi) {
    const int id   = blockIdx.x * 8 + (threadIdx.x >> 5);
    const int lane = threadIdx.x & 31;
    const int row  = id >> 4;
    const int k    = id & 15;
    const float* pr = Phi + (size_t)row * IN_DIM + k * CCOLS;

    int pos = 0;
    for (int c0 = 0; c0 < CCOLS; c0 += 32) {
        float v = pr[c0 + lane];
        unsigned m = __ballot_sync(0xffffffffu, v != 0.0f);
        if (v != 0.0f) {
            int p = pos + __popc(m & ((1u << lane) - 1u));
            uint32_t ent = (uint32_t)(k * CCOLS + c0 + lane - k * CCOLS) * COLBYTES
                         | (__float_as_uint(v) & 0x80000000u);
            // (local col = c0+lane)
            ent = (uint32_t)(c0 + lane) * COLBYTES | (__float_as_uint(v) & 0x80000000u);
            if (p < 4)            g_fix[k][row][p] = ent;
            else if (p < 4 + OVS) g_ovstage[row][k][p - 4] = ent | (uint32_t)((row & 7) << 1);
            g_mag = fabsf(v);                 // identical value from every writer
        }
        pos += __popc(m);
    }
    if (pos < 4 && lane < 4 - pos) g_fix[k][row][pos + lane] = DUMMY_OFF;
    int ov = pos - 4; if (ov < 0) ov = 0; if (ov > OVS) ov = OVS;
    if (lane == 0) g_ovscnt[row][k] = (uint8_t)ov;
}

// ---------------------------------------------------------------------------
// Build B: pack overflow into per-(chunk, rblock, warp) buckets. Deterministic
// (serial per lane in row order). 64 warps, lane = warp-bucket.
// ---------------------------------------------------------------------------
__global__ void __launch_bounds__(1024) build_b() {
    const int wid  = blockIdx.x * 32 + (threadIdx.x >> 5);   // 0..63
    const int lane = threadIdx.x & 31;                       // bucket
    const int k    = wid >> 2;
    const int rbi  = wid & 3;
    const int rowb = rbi * RPC + lane * 8;
    int off = 0;
    for (int rl = 0; rl < 8; ++rl) {
        const int row = rowb + rl;
        const int c = g_ovscnt[row][k];
        for (int j = 0; j < c; ++j) {
            if (off < BKT) g_ov[k][rbi][lane][off] = g_ovstage[row][k][j];
            off++;
        }
    }
    g_ovc[k][rbi][lane] = (uint8_t)(off < BKT ? off : BKT);
}

// ---------------------------------------------------------------------------
// Main: CTA = (128 x-rows, 256 out-rows). Lane l gathers rows 4l..4l+3.
// Fixed 4 entries per (row,chunk): branch-free, 8x4 independent LDS.128 chains.
// Rare overflow drained per warp with 8-way-select accumulation.
// ---------------------------------------------------------------------------
__global__ void __launch_bounds__(THREADS, 1) jl_main(const float* __restrict__ x,
                                                      float* __restrict__ out) {
    extern __shared__ float xs[];
    char* sm = (char*)xs;
    const int tid  = threadIdx.x;
    const int lane = tid & 31;
    const int w    = tid >> 5;
    const int rbi  = blockIdx.x;           // r-split fastest: L2 reuse of x
    const int rb   = rbi * RPC;
    const int n0   = blockIdx.y * TILE_N;
    const int r0l  = w * RPW;

    const unsigned mb = __float_as_uint(g_mag);
    const char* xb = sm + lane * 16;

    if (tid < XSTRIDE) xs[CCOLS * XSTRIDE + tid] = 0.0f;    // zero dummy column

    float4 acc[RPW];
    #pragma unroll
    for (int i = 0; i < RPW; ++i) acc[i] = make_float4(0.f, 0.f, 0.f, 0.f);

    for (int k = 0; k < NCH; ++k) {
        __syncthreads();
        // ---- stage x chunk: warp w owns rows 4w..4w+3, lane = column ----
        {
            const float* xr = x + (size_t)(n0 + 4 * w) * IN_DIM + k * CCOLS;
            #pragma unroll
            for (int it = 0; it < CCOLS / 32; ++it) {
                const int c = it * 32 + lane;
                float f0 = xr[c];
                float f1 = xr[c + IN_DIM];
                float f2 = xr[c + 2 * IN_DIM];
                float f3 = xr[c + 3 * IN_DIM];
                *(float4*)&xs[c * XSTRIDE + 4 * w] = make_float4(f0, f1, f2, f3);
            }
        }
        // ---- stage fixed entries: 4 KB ----
        if (tid < 256)
            ((uint4*)(sm + ENT_OFF))[tid] = *((const uint4*)&g_fix[k][rb][0] + tid);
        __syncthreads();

        // ---- fixed gather: branch-free, fully unrolled ----
        #pragma unroll
        for (int rr = 0; rr < RPW; ++rr) {
            const uint4 E = *(const uint4*)(sm + ENT_OFF + (r0l + rr) * 16);
            float4 a = acc[rr];
            #define JL_DO(e) {                                                  \
                float4 f = *(const float4*)(xb + ((e) & 0x0003FFF0u));          \
                float mm = __uint_as_float(mb | ((e) & 0x80000000u));           \
                a.x = fmaf(f.x, mm, a.x); a.y = fmaf(f.y, mm, a.y);             \
                a.z = fmaf(f.z, mm, a.z); a.w = fmaf(f.w, mm, a.w); }
            JL_DO(E.x) JL_DO(E.y) JL_DO(E.z) JL_DO(E.w)
            #undef JL_DO
            acc[rr] = a;
        }

        // ---- overflow drain (avg ~1.4 entries per warp-chunk) ----
        {
            const int oc = g_ovc[k][rbi][w];
            const uint32_t* op = g_ov[k][rbi][w];
            for (int i = 0; i < oc; ++i) {
                const uint32_t e = __ldg(op + i);
                float4 f = *(const float4*)(xb + (e & 0x0003FFF0u));
                float mm = __uint_as_float(mb | (e & 0x80000000u));
                const int rr = (int)((e >> 1) & 7u);
                #pragma unroll
                for (int j = 0; j < RPW; ++j) {
                    float mj = (rr == j) ? mm : 0.0f;
                    acc[j].x = fmaf(f.x, mj, acc[j].x);
                    acc[j].y = fmaf(f.y, mj, acc[j].y);
                    acc[j].z = fmaf(f.z, mj, acc[j].z);
                    acc[j].w = fmaf(f.w, mj, acc[j].w);
                }
            }
        }
    }

    // ---- epilogue: stage via smem (stride 257), coalesced float4 STG ----
    __syncthreads();
    #pragma unroll
    for (int rr = 0; rr < RPW; ++rr) {
        const int rl = r0l + rr;
        float4 a = acc[rr];
        xs[(4 * lane + 0) * OUT_STRIDE + rl] = a.x;
        xs[(4 * lane + 1) * OUT_STRIDE + rl] = a.y;
        xs[(4 * lane + 2) * OUT_STRIDE + rl] = a.z;
        xs[(4 * lane + 3) * OUT_STRIDE + rl] = a.w;
    }
    __syncthreads();
    {
        const int mq = tid & 63;
        #pragma unroll
        for (int row = tid >> 6; row < TILE_N; row += 16) {
            float4 v;
            v.x = xs[row * OUT_STRIDE + 4 * mq + 0];
            v.y = xs[row * OUT_STRIDE + 4 * mq + 1];
            v.z = xs[row * OUT_STRIDE + 4 * mq + 2];
            v.w = xs[row * OUT_STRIDE + 4 * mq + 3];
            *(float4*)(out + (size_t)(n0 + row) * OUT_DIM + rb + 4 * mq) = v;
        }
    }
}

// ---------------------------------------------------------------------------
extern "C" void kernel_launch(void* const* d_in, const int* in_sizes, int n_in,
                              void* d_out, int out_size) {
    const float* x   = (const float*)d_in[0];
    const float* Phi = (const float*)d_in[1];
    if (n_in >= 2 && in_sizes[0] == OUT_DIM * IN_DIM &&
        in_sizes[1] == N_ROWS * IN_DIM) {
        x   = (const float*)d_in[1];
        Phi = (const float*)d_in[0];
    }
    float* out = (float*)d_out;

    build_a<<<(OUT_DIM * NCH) / 8, 256>>>(Phi);   // 16384 warps
    build_b<<<2, 1024>>>();

    cudaFuncSetAttribute(jl_main, cudaFuncAttributeMaxDynamicSharedMemorySize,
                         SMEM_TOTAL);
    jl_main<<<dim3(NRB, N_ROWS / TILE_N), THREADS, SMEM_TOTAL>>>(x, out);
}

// round 12
// speedup vs baseline: 1.3003x; 1.3003x over previous
#include <cuda_runtime.h>
#include <cstdint>

#define IN_DIM   4096
#define OUT_DIM  1024
#define N_ROWS   16384
#define NCH      16
#define CCOLS    256
#define TILE_N   128
#define XSTRIDE  148                    // words/col: %32==20 -> conflict-free STS/LDS.128
#define COLBYTES (XSTRIDE * 4)          // 592
#define XS_BYTES (CCOLS * COLBYTES)     // 151552 (no dummy column needed)
#define ENT_OFF  XS_BYTES               // 16B aligned
#define SLOTP    8                      // pairs per (row,chunk) = 16 entries (Poisson(2.5) safe)
#define ENT_BYTES (256 * SLOTP * 16)    // 32 KB
#define SMEM_TOTAL (ENT_OFF + ENT_BYTES)  // 184320 B
#define OUT_STRIDE 257
#define THREADS  1024
#define RPC      256
#define RPW      8
#define NRB      (OUT_DIM / RPC)

// pair = {x-tile byte offset, multiplier bits (the Phi value itself)}; dummy = {0, 0.0f}
__device__ uint2   g_pair[NCH][OUT_DIM][2 * SLOTP];   // 2 MB, L2-resident
__device__ uint8_t g_pc[NCH][OUT_DIM];                // pair count

// ---------------------------------------------------------------------------
// Build: one warp per (row, chunk). Loads first (MLP=8), then ballots.
// Deterministic (ballot/popc in column order).
// ---------------------------------------------------------------------------
__global__ void __launch_bounds__(256) build_a(const float* __restrict__ Phi) {
    const int id   = blockIdx.x * 8 + (threadIdx.x >> 5);
    const int lane = threadIdx.x & 31;
    const int row  = id >> 4;
    const int k    = id & 15;
    const float* pr = Phi + (size_t)row * IN_DIM + k * CCOLS;

    float v[8];
    #pragma unroll
    for (int i = 0; i < 8; ++i) v[i] = pr[i * 32 + lane];   // independent loads

    int pos = 0;
    #pragma unroll
    for (int i = 0; i < 8; ++i) {
        unsigned m = __ballot_sync(0xffffffffu, v[i] != 0.0f);
        if (v[i] != 0.0f) {
            int p = pos + __popc(m & ((1u << lane) - 1u));
            if (p < 2 * SLOTP)
                g_pair[k][row][p] = make_uint2((uint32_t)(i * 32 + lane) * COLBYTES,
                                               __float_as_uint(v[i]));
        }
        pos += __popc(m);
    }
    if (pos & 1) {                         // pad to even with zero-mult dummy
        if (lane == 0 && pos < 2 * SLOTP) g_pair[k][row][pos] = make_uint2(0u, 0u);
        pos++;
    }
    if (pos > 2 * SLOTP) pos = 2 * SLOTP;  // statistically unreachable clamp
    if (lane == 0) g_pc[k][row] = (uint8_t)(pos >> 1);
}

// ---------------------------------------------------------------------------
// Main: CTA = (128 x-rows, 256 out-rows). Lane l gathers rows 4l..4l+3 (LDS.128).
// Entry pairs carry their multipliers: no decode. Counts via one 8B LDG/warp/chunk.
// ---------------------------------------------------------------------------
__global__ void __launch_bounds__(THREADS, 1) jl_main(const float* __restrict__ x,
                                                      float* __restrict__ out) {
    extern __shared__ float xs[];
    char* sm = (char*)xs;
    const int tid  = threadIdx.x;
    const int lane = tid & 31;
    const int w    = tid >> 5;
    const int rbi  = blockIdx.x;           // r-split fastest: L2 reuse of x
    const int rb   = rbi * RPC;
    const int n0   = blockIdx.y * TILE_N;
    const int r0l  = w * RPW;

    const char* xb = sm + lane * 16;       // this lane's 4-row base

    float4 acc[RPW];
    #pragma unroll
    for (int i = 0; i < RPW; ++i) acc[i] = make_float4(0.f, 0.f, 0.f, 0.f);

    for (int k = 0; k < NCH; ++k) {
        // counts for this warp's 8 rows: one 8B load, issued before the sync
        const uint2 cw = __ldg((const uint2*)&g_pc[k][rb + r0l]);

        __syncthreads();
        // ---- stage x chunk: warp w owns rows 4w..4w+3, lane = column ----
        {
            const float* xr = x + (size_t)(n0 + 4 * w) * IN_DIM + k * CCOLS;
            #pragma unroll
            for (int it = 0; it < CCOLS / 32; ++it) {
                const int c = it * 32 + lane;
                float f0 = xr[c];
                float f1 = xr[c + IN_DIM];
                float f2 = xr[c + 2 * IN_DIM];
                float f3 = xr[c + 3 * IN_DIM];
                *(float4*)&xs[c * XSTRIDE + 4 * w] = make_float4(f0, f1, f2, f3);
            }
        }
        // ---- stage entry pairs: 32 KB ----
        {
            const uint4* src = (const uint4*)&g_pair[k][rb][0];
            uint4* dst = (uint4*)(sm + ENT_OFF);
            dst[tid]           = src[tid];
            dst[tid + THREADS] = src[tid + THREADS];
        }
        __syncthreads();

        // ---- gather: warp sweeps its 8 out-rows ----
        #pragma unroll
        for (int rr = 0; rr < RPW; ++rr) {
            const int pairs = (int)((rr < 4 ? cw.x : cw.y) >> ((rr & 3) * 8)) & 0xFF;
            const uint4* eb = (const uint4*)(sm + ENT_OFF + (r0l + rr) * (SLOTP * 16));
            float4 a = acc[rr];
            for (int p = 0; p < pairs; ++p) {
                const uint4 E = eb[p];                  // {off0, mult0, off1, mult1}
                {
                    float4 f = *(const float4*)(xb + E.x);
                    float mm = __uint_as_float(E.y);
                    a.x = fmaf(f.x, mm, a.x); a.y = fmaf(f.y, mm, a.y);
                    a.z = fmaf(f.z, mm, a.z); a.w = fmaf(f.w, mm, a.w);
                }
                {
                    float4 f = *(const float4*)(xb + E.z);
                    float mm = __uint_as_float(E.w);
                    a.x = fmaf(f.x, mm, a.x); a.y = fmaf(f.y, mm, a.y);
                    a.z = fmaf(f.z, mm, a.z); a.w = fmaf(f.w, mm, a.w);
                }
            }
            acc[rr] = a;
        }
    }

    // ---- epilogue: stage via smem (stride 257), coalesced float4 STG ----
    __syncthreads();
    #pragma unroll
    for (int rr = 0; rr < RPW; ++rr) {
        const int rl = r0l + rr;
        float4 a = acc[rr];
        xs[(4 * lane + 0) * OUT_STRIDE + rl] = a.x;
        xs[(4 * lane + 1) * OUT_STRIDE + rl] = a.y;
        xs[(4 * lane + 2) * OUT_STRIDE + rl] = a.z;
        xs[(4 * lane + 3) * OUT_STRIDE + rl] = a.w;
    }
    __syncthreads();
    {
        const int mq = tid & 63;
        #pragma unroll
        for (int row = tid >> 6; row < TILE_N; row += 16) {
            float4 v;
            v.x = xs[row * OUT_STRIDE + 4 * mq + 0];
            v.y = xs[row * OUT_STRIDE + 4 * mq + 1];
            v.z = xs[row * OUT_STRIDE + 4 * mq + 2];
            v.w = xs[row * OUT_STRIDE + 4 * mq + 3];
            *(float4*)(out + (size_t)(n0 + row) * OUT_DIM + rb + 4 * mq) = v;
        }
    }
}

// ---------------------------------------------------------------------------
extern "C" void kernel_launch(void* const* d_in, const int* in_sizes, int n_in,
                              void* d_out, int out_size) {
    const float* x   = (const float*)d_in[0];
    const float* Phi = (const float*)d_in[1];
    if (n_in >= 2 && in_sizes[0] == OUT_DIM * IN_DIM &&
        in_sizes[1] == N_ROWS * IN_DIM) {
        x   = (const float*)d_in[1];
        Phi = (const float*)d_in[0];
    }
    float* out = (float*)d_out;

    build_a<<<(OUT_DIM * NCH) / 8, 256>>>(Phi);

    cudaFuncSetAttribute(jl_main, cudaFuncAttributeMaxDynamicSharedMemorySize,
                         SMEM_TOTAL);
    jl_main<<<dim3(NRB, N_ROWS / TILE_N), THREADS, SMEM_TOTAL>>>(x, out);
}